// round 8
// baseline (speedup 1.0000x reference)
#include <cuda_runtime.h>
#include <math.h>

// LIF_R step, N=8192. w @ g dominates: 256 MB fp32 streamed once from HBM.
// R6 candidate (3rd submission after two broker failures): R5 skeleton
// (512 CTAs x 8 warps, exactly 2 rows per warp, barrier-free, g staged in
// smem) + 8 front-batched LDG.128 per loop step to double per-warp MLP
// (R5 sat marginally at the in-flight-bytes requirement; DRAM stuck at 68%).

#define N_NEURONS 8192
#define NF4 (N_NEURONS / 4)          // 2048 float4 per row
#define THREADS 256
#define WARPS_PER_CTA 8
#define GRID 512                      // 4096 warps -> exactly 2 rows/warp
#define HALF 4096

#define C_M_INV 20.0f
#define F_V 0.15f
#define DELTA_V 12.0f

__global__ __launch_bounds__(THREADS, 4)
void lif_r_kernel(const float* __restrict__ x_in,
                  const float* __restrict__ v,
                  const float* __restrict__ g,
                  const float* __restrict__ theta_s,
                  const float* __restrict__ w,
                  const float* __restrict__ v_rest,
                  float* __restrict__ out)
{
    __shared__ float sg[N_NEURONS];   // 32 KB

    {
        const float4* g4 = reinterpret_cast<const float4*>(g);
        float4* s4 = reinterpret_cast<float4*>(sg);
        for (int i = threadIdx.x; i < NF4; i += THREADS)
            s4[i] = g4[i];
    }
    __syncthreads();

    const int lane = threadIdx.x & 31;
    const int wid  = threadIdx.x >> 5;
    const int row0 = blockIdx.x * WARPS_PER_CTA + wid;   // 0..4095
    const int row1 = row0 + HALF;                        // 4096..8191

    const float4* __restrict__ sg4 = reinterpret_cast<const float4*>(sg);
    const float4* __restrict__ wr0 =
        reinterpret_cast<const float4*>(w + (size_t)row0 * N_NEURONS);
    const float4* __restrict__ wr1 =
        reinterpret_cast<const float4*>(w + (size_t)row1 * N_NEURONS);

    // 2048 f4 / 32 lanes = 64 iters/lane; stride 128 -> 16 outer steps,
    // 8 LDG.128 front-batched per step (4 offsets x 2 rows).
    float a0 = 0.0f, a1 = 0.0f, b0 = 0.0f, b1 = 0.0f;
    for (int i = lane; i < NF4; i += 128) {
        float4 wa0 = __ldcs(&wr0[i]);
        float4 wa1 = __ldcs(&wr0[i + 32]);
        float4 wa2 = __ldcs(&wr0[i + 64]);
        float4 wa3 = __ldcs(&wr0[i + 96]);
        float4 wb0 = __ldcs(&wr1[i]);
        float4 wb1 = __ldcs(&wr1[i + 32]);
        float4 wb2 = __ldcs(&wr1[i + 64]);
        float4 wb3 = __ldcs(&wr1[i + 96]);

        float4 gv;
        gv = sg4[i];
        a0 = fmaf(wa0.x, gv.x, a0); a0 = fmaf(wa0.y, gv.y, a0);
        a0 = fmaf(wa0.z, gv.z, a0); a0 = fmaf(wa0.w, gv.w, a0);
        b0 = fmaf(wb0.x, gv.x, b0); b0 = fmaf(wb0.y, gv.y, b0);
        b0 = fmaf(wb0.z, gv.z, b0); b0 = fmaf(wb0.w, gv.w, b0);
        gv = sg4[i + 32];
        a1 = fmaf(wa1.x, gv.x, a1); a1 = fmaf(wa1.y, gv.y, a1);
        a1 = fmaf(wa1.z, gv.z, a1); a1 = fmaf(wa1.w, gv.w, a1);
        b1 = fmaf(wb1.x, gv.x, b1); b1 = fmaf(wb1.y, gv.y, b1);
        b1 = fmaf(wb1.z, gv.z, b1); b1 = fmaf(wb1.w, gv.w, b1);
        gv = sg4[i + 64];
        a0 = fmaf(wa2.x, gv.x, a0); a0 = fmaf(wa2.y, gv.y, a0);
        a0 = fmaf(wa2.z, gv.z, a0); a0 = fmaf(wa2.w, gv.w, a0);
        b0 = fmaf(wb2.x, gv.x, b0); b0 = fmaf(wb2.y, gv.y, b0);
        b0 = fmaf(wb2.z, gv.z, b0); b0 = fmaf(wb2.w, gv.w, b0);
        gv = sg4[i + 96];
        a1 = fmaf(wa3.x, gv.x, a1); a1 = fmaf(wa3.y, gv.y, a1);
        a1 = fmaf(wa3.z, gv.z, a1); a1 = fmaf(wa3.w, gv.w, a1);
        b1 = fmaf(wb3.x, gv.x, b1); b1 = fmaf(wb3.y, gv.y, b1);
        b1 = fmaf(wb3.z, gv.z, b1); b1 = fmaf(wb3.w, gv.w, b1);
    }
    float accA = a0 + a1;
    float accB = b0 + b1;

    #pragma unroll
    for (int off = 16; off > 0; off >>= 1) {
        accA += __shfl_xor_sync(0xFFFFFFFFu, accA, off);
        accB += __shfl_xor_sync(0xFFFFFFFFu, accB, off);
    }

    if (lane == 0) {
        {
            const float I  = accA + x_in[row0];
            const float vv = v[row0];
            const float vr = v_rest[row0];
            const float th = theta_s[row0];
            const float v_next = vv + (vr - vv + I * C_M_INV);
            const float soft = 1.0f / (1.0f + expf(-(v_next - th)));
            const bool spiked = (v_next >= th);
            const float v_reset = vr + F_V * (vv - vr) - DELTA_V;
            out[row0] = spiked ? v_reset : v_next;
            out[N_NEURONS + row0] = soft;
        }
        {
            const float I  = accB + x_in[row1];
            const float vv = v[row1];
            const float vr = v_rest[row1];
            const float th = theta_s[row1];
            const float v_next = vv + (vr - vv + I * C_M_INV);
            const float soft = 1.0f / (1.0f + expf(-(v_next - th)));
            const bool spiked = (v_next >= th);
            const float v_reset = vr + F_V * (vv - vr) - DELTA_V;
            out[row1] = spiked ? v_reset : v_next;
            out[N_NEURONS + row1] = soft;
        }
    }
}

extern "C" void kernel_launch(void* const* d_in, const int* in_sizes, int n_in,
                              void* d_out, int out_size)
{
    // metadata order: x_in, v, g, theta_s, w, v_rest, tau_g
    const float* x_in    = (const float*)d_in[0];
    const float* v       = (const float*)d_in[1];
    const float* g       = (const float*)d_in[2];
    const float* theta_s = (const float*)d_in[3];
    const float* w       = (const float*)d_in[4];
    const float* v_rest  = (const float*)d_in[5];
    float* out = (float*)d_out;

    lif_r_kernel<<<GRID, THREADS>>>(x_in, v, g, theta_s, w, v_rest, out);
}